// round 14
// baseline (speedup 1.0000x reference)
#include <cuda_runtime.h>
#include <math.h>

// predicts/targets (2,4,64,256,256) f32, masks (2,1,64,256,256) f32 -> scalar f32.
// Identities (validated R2..R12, rel_err ~1e-7):
//   omega_pred - omega_trgt = vorticity(scale*(P-T));  scale/(2*delta)=1
//   voxel counts & contributes <=> all 27 masks in 3x3x3 neighborhood == 1
// R13 = R9 config with 2 planes per barrier period: 14-LDG batches, half the
//       barriers/drains per plane; u/v depth-4, w depth-2, CP depth-2; masks
//       rolled in stager registers.
namespace {
constexpr int Bn = 2, Cn = 4, Dn = 64, Hn = 256, Wn = 256;
constexpr long long CH = (long long)Dn * Hn * Wn;
constexpr int HW  = Hn * Wn;
constexpr int TY  = 7;                   // output rows per block
constexpr int RWS = 9;                   // staged rows (TY + 2 halo)
constexpr int NYT = 37;                  // 37*7 = 259 >= 254
constexpr int ZC  = 4;                   // z-chunks per batch {16,16,16,14} (even)
constexpr int NBLK = NYT * 2 * ZC;       // 296 = 2 blocks/SM * 148 SMs
constexpr int PLF  = RWS * Wn;           // 2304 elems per staged plane
// dynamic smem layout (floats/bytes)
constexpr int SMEM_BYTES = (4 + 4 + 2) * PLF * 4 + 2 * PLF;   // 96768 B
}

__device__ float        g_psum[NBLK];
__device__ unsigned int g_pcnt[NBLK];
__device__ unsigned int g_ticket = 0;

__device__ __forceinline__ float4 f4sub(const float4 a, const float4 b) {
    return make_float4(a.x - b.x, a.y - b.y, a.z - b.z, a.w - b.w);
}
__device__ __forceinline__ unsigned packm(const float4 m) {
    return (m.x > 0.5f ? 1u : 0u)       | (m.y > 0.5f ? 1u : 0u) << 8
         | (m.z > 0.5f ? 1u : 0u) << 16 | (m.w > 0.5f ? 1u : 0u) << 24;
}

__global__ __launch_bounds__(512, 2)
void k_main(const float* __restrict__ P,
            const float* __restrict__ T,
            const float* __restrict__ M,
            float* __restrict__ out) {
    extern __shared__ float smemf[];
    float*         sU  = smemf;                    // 4 planes (slot p&3)
    float*         sV  = sU + 4 * PLF;             // 4 planes
    float*         sW  = sV + 4 * PLF;             // 2 planes (slot p&1)
    unsigned char* sCP = (unsigned char*)(sW + 2 * PLF);  // 2 byte planes

    const int tid = threadIdx.x;
    const int b   = blockIdx.y / ZC;
    const int zi  = blockIdx.y % ZC;
    const int z0  = 1 + zi * 16;
    const int len = (zi < 3) ? 16 : 14;            // even chunk lengths
    const int y0  = 1 + blockIdx.x * TY;

    const float* mb = M + (long long)b * CH;
    const float* uP = P + ((long long)b * Cn + 1) * CH;
    const float* uT = T + ((long long)b * Cn + 1) * CH;
    const float* vP = uP + CH;  const float* vT = uT + CH;
    const float* wP = vP + CH;  const float* wT = vT + CH;

    // staging slot A (all 512 threads) + slot B (tid&7==0 covers 64 extra slots)
    const int  rA  = tid >> 6, x4A = (tid & 63) << 2;
    const int  roA = rA * Wn + x4A;
    const long long rbA = (long long)min(y0 - 1 + rA, Hn - 1) * Wn + x4A;
    const bool hasB = (tid & 7) == 0;
    const int  sB  = 512 + (tid >> 3);
    const int  roB = (sB >> 6) * Wn + ((sB & 63) << 2);
    const long long rbB = (long long)min(y0 + 7, Hn - 1) * Wn + ((sB & 63) << 2);

    // rolling packed masks per slot: m0 = m(z-1), m1 = m(z)
    unsigned mA0, mA1, mB0 = 0u, mB1 = 0u;

    // ---- prologue: u,v planes z0-1, z0 ; mask regs ----
    #pragma unroll
    for (int k = 0; k < 2; ++k) {
        const int zz = z0 - 1 + k, su = zz & 3;
        const long long pb = (long long)zz * HW + rbA;
        *(float4*)(sU + su * PLF + roA) = f4sub(*(const float4*)(uP + pb), *(const float4*)(uT + pb));
        *(float4*)(sV + su * PLF + roA) = f4sub(*(const float4*)(vP + pb), *(const float4*)(vT + pb));
        const unsigned m = packm(*(const float4*)(mb + pb));
        if (k == 0) mA0 = m; else mA1 = m;
        if (hasB) {
            const long long pbx = (long long)zz * HW + rbB;
            *(float4*)(sU + su * PLF + roB) = f4sub(*(const float4*)(uP + pbx), *(const float4*)(uT + pbx));
            *(float4*)(sV + su * PLF + roB) = f4sub(*(const float4*)(vP + pbx), *(const float4*)(vT + pbx));
            const unsigned mx = packm(*(const float4*)(mb + pbx));
            if (k == 0) mB0 = mx; else mB1 = mx;
        }
    }
    // (first in-loop barrier orders prologue STS before any consume)

    // Stage planes z+1, z+2 of u,v ; z, z+1 of w ; CP(z), CP(z+1).
    auto stagePair = [&](int z, int ro, long long rowb, unsigned& m0, unsigned& m1) {
        const long long pz  = (long long)z * HW + rowb;
        const long long pz1 = pz + HW;
        const long long pz2 = pz + 2 * HW;
        // batched LDGs (compiler front-batches as regs permit)
        const float4 u1p = *(const float4*)(uP + pz1), u1t = *(const float4*)(uT + pz1);
        const float4 u2p = *(const float4*)(uP + pz2), u2t = *(const float4*)(uT + pz2);
        const float4 v1p = *(const float4*)(vP + pz1), v1t = *(const float4*)(vT + pz1);
        const float4 v2p = *(const float4*)(vP + pz2), v2t = *(const float4*)(vT + pz2);
        const float4 w0p = *(const float4*)(wP + pz),  w0t = *(const float4*)(wT + pz);
        const float4 w1p = *(const float4*)(wP + pz1), w1t = *(const float4*)(wT + pz1);
        const float4 m1v = *(const float4*)(mb + pz1);
        const float4 m2v = *(const float4*)(mb + pz2);

        *(float4*)(sU + ((z + 1) & 3) * PLF + ro) = f4sub(u1p, u1t);
        *(float4*)(sU + ((z + 2) & 3) * PLF + ro) = f4sub(u2p, u2t);
        *(float4*)(sV + ((z + 1) & 3) * PLF + ro) = f4sub(v1p, v1t);
        *(float4*)(sV + ((z + 2) & 3) * PLF + ro) = f4sub(v2p, v2t);
        *(float4*)(sW + (z & 1) * PLF + ro)       = f4sub(w0p, w0t);
        *(float4*)(sW + ((z + 1) & 1) * PLF + ro) = f4sub(w1p, w1t);
        const unsigned mn1 = packm(m1v), mn2 = packm(m2v);
        *(unsigned*)(sCP + (z & 1) * PLF + ro)       = m0 & m1 & mn1;
        *(unsigned*)(sCP + ((z + 1) & 1) * PLF + ro) = m1 & mn1 & mn2;
        m0 = mn1; m1 = mn2;
    };

    float fs  = 0.f;
    int   cnt = 0;
    const int x    = tid & 255;
    const int half = tid >> 8;
    const int rlo  = (half == 0) ? 1 : 5;
    const int rhi  = (half == 0) ? 4 : 7;

    for (int z = z0; z < z0 + len; z += 2) {
        // ---- phase A: stage the pair ----
        stagePair(z, roA, rbA, mA0, mA1);
        if (hasB) stagePair(z, roB, rbB, mB0, mB1);
        __syncthreads();

        // ---- phase B: consume planes z and z+1 (R9 scalar consume) ----
        #pragma unroll
        for (int q = 0; q < 2; ++q) {
            const int pl  = z + q;
            const int sz  = pl & 3, szp = (pl + 1) & 3, szm = (pl - 1) & 3;
            const int swz = pl & 1;
            const unsigned char* cp = sCP + (pl & 1) * PLF;
            if (x >= 1 && x <= Wn - 2) {
                #pragma unroll
                for (int r = rlo; r <= rhi; ++r) {
                    const int y = y0 - 1 + r;
                    if (y > Hn - 2) break;
                    const int ok = (int)cp[(r - 1) * Wn + x - 1] & cp[(r - 1) * Wn + x]
                                 & cp[(r - 1) * Wn + x + 1]
                                 & cp[r * Wn + x - 1] & cp[r * Wn + x] & cp[r * Wn + x + 1]
                                 & cp[(r + 1) * Wn + x - 1] & cp[(r + 1) * Wn + x]
                                 & cp[(r + 1) * Wn + x + 1];

                    const float dyU = sU[sz * PLF + (r + 1) * Wn + x] - sU[sz * PLF + (r - 1) * Wn + x];
                    const float dzU = sU[szp * PLF + r * Wn + x]      - sU[szm * PLF + r * Wn + x];
                    const float dyW = sW[swz * PLF + (r + 1) * Wn + x] - sW[swz * PLF + (r - 1) * Wn + x];
                    const float dxW = sW[swz * PLF + r * Wn + x + 1]   - sW[swz * PLF + r * Wn + x - 1];
                    const float dxV = sV[sz * PLF + r * Wn + x + 1]    - sV[sz * PLF + r * Wn + x - 1];
                    const float dzV = sV[szp * PLF + r * Wn + x]       - sV[szm * PLF + r * Wn + x];

                    const float ox = dyW - dzV;
                    const float oy = dzU - dxW;
                    const float oz = dxV - dyU;
                    fs  += (float)ok * sqrtf(ox * ox + oy * oy + oz * oz);
                    cnt += ok;
                }
            }
        }
        __syncthreads();   // protects slot reuse by next iteration's stage
    }

    // ---- block reduction (16 warps) -> partial; last block finalizes ----
    #pragma unroll
    for (int off = 16; off; off >>= 1) {
        fs  += __shfl_down_sync(0xffffffffu, fs,  off);
        cnt += __shfl_down_sync(0xffffffffu, cnt, off);
    }
    __shared__ float ws[16];
    __shared__ int   wc2[16];
    __shared__ bool  sLast;
    const int wid = tid >> 5, lid = tid & 31;
    if (lid == 0) { ws[wid] = fs; wc2[wid] = cnt; }
    __syncthreads();
    if (wid == 0) {
        fs  = (lid < 16) ? ws[lid]  : 0.f;
        cnt = (lid < 16) ? wc2[lid] : 0;
        #pragma unroll
        for (int off = 8; off; off >>= 1) {
            fs  += __shfl_down_sync(0xffffffffu, fs,  off);
            cnt += __shfl_down_sync(0xffffffffu, cnt, off);
        }
        if (lid == 0) {
            const int slot = blockIdx.y * NYT + blockIdx.x;
            g_psum[slot] = fs;
            g_pcnt[slot] = (unsigned)cnt;
            __threadfence();
            const unsigned t = atomicAdd(&g_ticket, 1u);
            sLast = (t == NBLK - 1);
        }
    }
    __syncthreads();

    if (sLast) {
        // Deterministic final reduce: fixed order over 296 slots, double accum.
        double             s = (tid < NBLK) ? (double)__ldcg(&g_psum[tid]) : 0.0;
        unsigned long long c = (tid < NBLK) ? (unsigned long long)__ldcg(&g_pcnt[tid]) : 0ull;
        #pragma unroll
        for (int off = 16; off; off >>= 1) {
            s += __shfl_down_sync(0xffffffffu, s, off);
            c += __shfl_down_sync(0xffffffffu, c, off);
        }
        __shared__ double             ds[16];
        __shared__ unsigned long long dc[16];
        if (lid == 0) { ds[wid] = s; dc[wid] = c; }
        __syncthreads();
        if (wid == 0) {
            s = (lid < 16) ? ds[lid] : 0.0;
            c = (lid < 16) ? dc[lid] : 0ull;
            #pragma unroll
            for (int off = 8; off; off >>= 1) {
                s += __shfl_down_sync(0xffffffffu, s, off);
                c += __shfl_down_sync(0xffffffffu, c, off);
            }
            if (lid == 0) {
                out[0] = (float)(s / (double)c);
                g_ticket = 0;                      // reset for next graph replay
            }
        }
    }
}

extern "C" void kernel_launch(void* const* d_in, const int* in_sizes, int n_in,
                              void* d_out, int out_size) {
    const float* P = (const float*)d_in[0];
    const float* T = (const float*)d_in[1];
    const float* M = (const float*)d_in[2];
    float*       O = (float*)d_out;

    cudaFuncSetAttribute(k_main, cudaFuncAttributeMaxDynamicSharedMemorySize, SMEM_BYTES);
    k_main<<<dim3(NYT, 2 * ZC), 512, SMEM_BYTES>>>(P, T, M, O);
}